// round 7
// baseline (speedup 1.0000x reference)
#include <cuda_runtime.h>
#include <cuda_bf16.h>

#define BINS 32
#define CZ   128
#define NCLS 66              // 2*BINS + 2
#define LSEQ 768
#define NB   2
#define TPB  256
#define NCTAS (148 * 6)      // persistent grid: 6 CTAs/SM x 148 SMs
#define JCHUNK 96            // j-vectors per work chunk
#define NCHUNK (NB * LSEQ * (LSEQ / JCHUNK))   // 12288
#define NMW   (NB * LSEQ / 32)                 // 48 mask words

// Persistent-CTA version, smem trimmed to ~37KB so 6 CTAs/SM fit.
// Each CTA builds Wb=W+b (row 0 zeroed = mask sink), caches residue rows as
// int16 and the mask as a bitset, then grid-strides over 12288 chunks.
// Each warp stores one C_Z=128 float vector per j (LDS.128 -> STG.128 .cs).
__global__ __launch_bounds__(TPB) void relpos_kernel(
    const int*   __restrict__ ridx,   // [B, L] int32, values in [0, 1024)
    const int*   __restrict__ rmask,  // [B, L] bool widened to int32
    const float* __restrict__ W,      // [66, 128]
    const float* __restrict__ bias,   // [128]
    float*       __restrict__ out)    // [B, L, L, 128]
{
    __shared__ float    wb[NCLS * CZ];    // 33792 B; row 0 = zeros
    __shared__ short    rjs[NB * LSEQ];   // 3072 B
    __shared__ unsigned mbits[NMW];       // 192 B

    const int tid = threadIdx.x;

    // Wb table: row 0 (unused by valid classes, idx in [1,65]) = zeros
    #pragma unroll 4
    for (int k = tid; k < NCLS * CZ; k += TPB)
        wb[k] = (k < CZ) ? 0.0f : (W[k] + bias[k & (CZ - 1)]);

    for (int k = tid; k < NB * LSEQ; k += TPB)
        rjs[k] = (short)ridx[k];

    for (int w = tid; w < NMW; w += TPB) {
        unsigned m = 0;
        #pragma unroll
        for (int t = 0; t < 32; t++)
            m |= (unsigned)(rmask[w * 32 + t] != 0) << t;
        mbits[w] = m;
    }
    __syncthreads();

    const int lane = tid & 31;
    const int warp = tid >> 5;

    for (int c = blockIdx.x; c < NCHUNK; c += NCTAS) {
        const int row   = c >> 3;               // 0 .. B*L-1   (8 chunks/row)
        const int jbase = (c & 7) * JCHUNK;
        const int b     = row / LSEQ;
        const int i     = row - b * LSEQ;
        const int boff  = b * LSEQ;
        const int ri    = (int)rjs[boff + i];
        const unsigned miBit =
            (mbits[(boff + i) >> 5] >> ((boff + i) & 31)) & 1u;

        float4* orow = reinterpret_cast<float4*>(out)
                     + (size_t)row * LSEQ * (CZ / 4);

        // 96 j's / 8 warps = 12 iterations per warp
        #pragma unroll 2
        for (int t = warp; t < JCHUNK; t += TPB / 32) {
            const int j   = jbase + t;
            const int key = boff + j;
            int d = (int)rjs[key] - ri;
            d = min(max(d, -BINS), BINS) + BINS + 1;      // [1, 65]
            const int sel = (int)((mbits[key >> 5] >> (key & 31)) & miBit);
            d *= sel;                                      // masked -> row 0
            float4 v = *reinterpret_cast<const float4*>(&wb[d * CZ + lane * 4]);
            __stcs(&orow[(size_t)j * (CZ / 4) + lane], v);
        }
    }
}

extern "C" void kernel_launch(void* const* d_in, const int* in_sizes, int n_in,
                              void* d_out, int out_size) {
    const int*   ridx  = (const int*)d_in[0];
    const int*   rmask = (const int*)d_in[1];
    const float* W     = (const float*)d_in[2];
    const float* bias  = (const float*)d_in[3];
    float*       out   = (float*)d_out;

    relpos_kernel<<<NCTAS, TPB>>>(ridx, rmask, W, bias, out);
}

// round 8
// speedup vs baseline: 1.0502x; 1.0502x over previous
#include <cuda_runtime.h>
#include <cuda_bf16.h>

#define BINS 32
#define CZ   128
#define NCLS 66              // 2*BINS + 2
#define LSEQ 768
#define NB   2
#define TPB  256
#define NCTAS (148 * 5)      // persistent grid: 5 CTAs/SM x 148 SMs
#define JCHUNK 96            // j-vectors per work chunk
#define NCHUNK (NB * LSEQ * (LSEQ / JCHUNK))   // 12288

// Persistent-CTA kernel (R5 config, unroll 1). Each CTA builds Wb=W+b (row 0
// zeroed = mask sink), caches residue/mask rows for both batches, then
// grid-strides over 12288 (row, j-block) chunks. Each warp stores one C_Z=128
// float vector per j as 2x LDS.128 -> 2x STG.E.128 (.cs streaming), with a
// strictly serial per-warp store stream to minimize L1tex queue bursts.
__global__ __launch_bounds__(TPB) void relpos_kernel(
    const int*   __restrict__ ridx,   // [B, L] int32
    const int*   __restrict__ rmask,  // [B, L] bool widened to int32
    const float* __restrict__ W,      // [66, 128]
    const float* __restrict__ bias,   // [128]
    float*       __restrict__ out)    // [B, L, L, 128]
{
    __shared__ float         wb[NCLS * CZ];    // 33792 B; row 0 = zeros
    __shared__ int           rj[NB * LSEQ];    // 6144 B
    __shared__ unsigned char mj[NB * LSEQ];    // 1536 B

    const int tid = threadIdx.x;

    // Wb table: row 0 (unused by valid classes, idx in [1,65]) = zeros
    #pragma unroll 4
    for (int k = tid; k < NCLS * CZ; k += TPB)
        wb[k] = (k < CZ) ? 0.0f : (W[k] + bias[k & (CZ - 1)]);

    for (int k = tid; k < NB * LSEQ; k += TPB) {
        rj[k] = ridx[k];
        mj[k] = (unsigned char)(rmask[k] != 0);
    }
    __syncthreads();

    const int lane = tid & 31;
    const int warp = tid >> 5;

    for (int c = blockIdx.x; c < NCHUNK; c += NCTAS) {
        const int row   = c >> 3;               // 0 .. B*L-1   (8 chunks/row)
        const int jbase = (c & 7) * JCHUNK;
        const int b     = row / LSEQ;
        const int i     = row - b * LSEQ;
        const int boff  = b * LSEQ;
        const int ri    = rj[boff + i];
        const bool mi   = (mj[boff + i] != 0);

        float4* orow = reinterpret_cast<float4*>(out)
                     + (size_t)row * LSEQ * (CZ / 4);

        // 96 j's / 8 warps = 12 iterations per warp, serial store stream
        #pragma unroll 1
        for (int t = warp; t < JCHUNK; t += TPB / 32) {
            const int j = jbase + t;
            int d = rj[boff + j] - ri;
            d = min(max(d, -BINS), BINS) + BINS + 1;      // [1, 65]
            if (!(mi && (mj[boff + j] != 0))) d = 0;      // masked -> zero row
            float4 v = *reinterpret_cast<const float4*>(&wb[d * CZ + lane * 4]);
            __stcs(&orow[(size_t)j * (CZ / 4) + lane], v);
        }
    }
}

extern "C" void kernel_launch(void* const* d_in, const int* in_sizes, int n_in,
                              void* d_out, int out_size) {
    const int*   ridx  = (const int*)d_in[0];
    const int*   rmask = (const int*)d_in[1];
    const float* W     = (const float*)d_in[2];
    const float* bias  = (const float*)d_in[3];
    float*       out   = (float*)d_out;

    relpos_kernel<<<NCTAS, TPB>>>(ridx, rmask, W, bias, out);
}